// round 8
// baseline (speedup 1.0000x reference)
#include <cuda_runtime.h>
#include <cstdint>

// RVQ: x[B,S,768] f32, codebook[3,16,256] f32, alpha scalar.
// Per token, per head: argmax_c (x·k_c - 0.5||k_c||^2)  (== argmin sq-dist)
// out = alpha*x + (1-alpha)*k[best]; code = b0 + 16*b1 + 256*b2 (as f32).
//
// Scheme A skeleton, tuned for occupancy: TPW=2 -> ~90 regs -> 6 blocks/SM
// (24 warps). Swizzled conflict-free codebook LDS, front-batched x LDG,
// 16-value split-exchange + REDUX argmax.

#define NH   3
#define NC   16
#define DHD  256
#define DFULL 768
#define NF4  64             // float4 per code row
#define TPW  2              // tokens per warp
#define NWARPS 4
#define TPB  (TPW * NWARPS) // 8 tokens per block tile
#define FULLMASK 0xffffffffu

__device__ __forceinline__ int swz(int j) { return j ^ (j >> 3); }

__device__ __forceinline__ unsigned fmono(float f) {
    int b = __float_as_int(f);
    return (unsigned)(b ^ ((b >> 31) | 0x80000000));
}

__global__ void __launch_bounds__(128, 6) rvq_kernel(
    const float* __restrict__ x,
    const float* __restrict__ cb,
    const float* __restrict__ alphap,
    float* __restrict__ out,
    float* __restrict__ code_out,
    int tokens, int write_code, int ntiles)
{
    // XOR-swizzled codebook: lane L reads swz(2L), swz(2L+1) conflict-free.
    __shared__ float4 scb[NH * NC * NF4];   // 48 KB

    const int tid = threadIdx.x;
    {
        const float4* cbg = (const float4*)cb;
        #pragma unroll
        for (int g = tid; g < NH * NC * NF4; g += 128) {
            int r = g >> 6, j = g & 63;
            scb[(r << 6) + swz(j)] = cbg[g];
        }
    }
    __syncthreads();

    const int lane = tid & 31;
    const int warp = tid >> 5;
    const int cm   = (lane >> 1) & 15;     // code this lane owns after reduce
    const int sA   = swz(2 * lane);        // lane-constant swizzled offsets
    const int sB   = swz(2 * lane + 1);

    // Half squared norm of code cm, per head (one-time).
    float hn[NH];
    #pragma unroll
    for (int h = 0; h < NH; h++) {
        const float4* row = &scb[(h * NC + cm) << 6];
        float s = 0.f;
        #pragma unroll
        for (int j = 0; j < NF4; j++) {
            float4 k = row[swz((j + 4 * cm) & 63)];
            s = fmaf(k.x, k.x, s); s = fmaf(k.y, k.y, s);
            s = fmaf(k.z, k.z, s); s = fmaf(k.w, k.w, s);
        }
        hn[h] = 0.5f * s;
    }

    const float alpha = *alphap;
    const float beta  = 1.0f - alpha;

    for (int tile = blockIdx.x; tile < ntiles; tile += gridDim.x) {
        int t0 = tile * TPB + warp * TPW;
        if (t0 > tokens - TPW) t0 = tokens - TPW;   // overlap tail: same values
        if (t0 < 0) t0 = 0;

        int pack[TPW];
        #pragma unroll
        for (int t = 0; t < TPW; t++) pack[t] = 0;

        #pragma unroll
        for (int h = 0; h < NH; h++) {
            // Front-batched x: lane holds 8 contiguous dims of head h.
            float4 xa[TPW], xb[TPW];
            const float4* xp0 = (const float4*)(x + t0 * DFULL + h * DHD)
                                + (lane << 1);
            #pragma unroll
            for (int t = 0; t < TPW; t++) {
                xa[t] = xp0[t * 192];
                xb[t] = xp0[t * 192 + 1];
            }

            float acc[TPW][NC];
            #pragma unroll
            for (int t = 0; t < TPW; t++)
                #pragma unroll
                for (int c = 0; c < NC; c++) acc[t][c] = 0.f;

            const float4* hbase = &scb[(h * NC) << 6];
            #pragma unroll
            for (int c = 0; c < NC; c++) {
                float4 ka = hbase[(c << 6) + sA];
                float4 kb = hbase[(c << 6) + sB];
                #pragma unroll
                for (int t = 0; t < TPW; t++) {
                    float a = acc[t][c];
                    a = fmaf(xa[t].x, ka.x, a);
                    a = fmaf(xa[t].y, ka.y, a);
                    a = fmaf(xa[t].z, ka.z, a);
                    a = fmaf(xa[t].w, ka.w, a);
                    a = fmaf(xb[t].x, kb.x, a);
                    a = fmaf(xb[t].y, kb.y, a);
                    a = fmaf(xb[t].z, kb.z, a);
                    a = fmaf(xb[t].w, kb.w, a);
                    acc[t][c] = a;
                }
            }

            // Per token: 16-value split-exchange (16 shfl) + REDUX argmax.
            #pragma unroll
            for (int t = 0; t < TPW; t++) {
                float w8[8];
                {
                    const bool up = (lane & 16) != 0;
                    #pragma unroll
                    for (int j = 0; j < 8; j++) {
                        float snd = up ? acc[t][j]     : acc[t][j + 8];
                        float kp  = up ? acc[t][j + 8] : acc[t][j];
                        w8[j] = kp + __shfl_xor_sync(FULLMASK, snd, 16);
                    }
                }
                float w4[4];
                {
                    const bool up = (lane & 8) != 0;
                    #pragma unroll
                    for (int j = 0; j < 4; j++) {
                        float snd = up ? w8[j]     : w8[j + 4];
                        float kp  = up ? w8[j + 4] : w8[j];
                        w4[j] = kp + __shfl_xor_sync(FULLMASK, snd, 8);
                    }
                }
                float w2[2];
                {
                    const bool up = (lane & 4) != 0;
                    #pragma unroll
                    for (int j = 0; j < 2; j++) {
                        float snd = up ? w4[j]     : w4[j + 2];
                        float kp  = up ? w4[j + 2] : w4[j];
                        w2[j] = kp + __shfl_xor_sync(FULLMASK, snd, 4);
                    }
                }
                float w1;
                {
                    const bool up = (lane & 2) != 0;
                    float snd = up ? w2[0] : w2[1];
                    float kp  = up ? w2[1] : w2[0];
                    w1 = kp + __shfl_xor_sync(FULLMASK, snd, 2);
                }
                w1 += __shfl_xor_sync(FULLMASK, w1, 1);

                float sc = w1 - hn[h];   // lane holds score of code cm
                unsigned u = fmono(sc);
                unsigned umax = __reduce_max_sync(FULLMASK, u);
                unsigned cand = (u == umax) ? (unsigned)cm : 64u;
                int bi = (int)__reduce_min_sync(FULLMASK, cand);
                pack[t] += bi << (4 * h);

                const float4* row = hbase + (bi << 6);
                float4 ka = row[sA];
                float4 kb = row[sB];
                float4 oa, ob;
                oa.x = fmaf(alpha, xa[t].x, beta * ka.x);
                oa.y = fmaf(alpha, xa[t].y, beta * ka.y);
                oa.z = fmaf(alpha, xa[t].z, beta * ka.z);
                oa.w = fmaf(alpha, xa[t].w, beta * ka.w);
                ob.x = fmaf(alpha, xb[t].x, beta * kb.x);
                ob.y = fmaf(alpha, xb[t].y, beta * kb.y);
                ob.z = fmaf(alpha, xb[t].z, beta * kb.z);
                ob.w = fmaf(alpha, xb[t].w, beta * kb.w);
                float4* op = (float4*)(out + (t0 + t) * DFULL + h * DHD)
                             + (lane << 1);
                op[0] = oa;
                op[1] = ob;
            }
        }

        if (write_code && lane == 0) {
            #pragma unroll
            for (int t = 0; t < TPW; t++)
                code_out[t0 + t] = (float)pack[t];
        }
    }
}

extern "C" void kernel_launch(void* const* d_in, const int* in_sizes, int n_in,
                              void* d_out, int out_size)
{
    const float* x      = (const float*)d_in[0];
    const float* kernel = (const float*)d_in[1];
    const float* alpha  = (const float*)d_in[2];
    float* out = (float*)d_out;

    const int tokens = in_sizes[0] / DFULL;        // B*S
    const int ntiles = (tokens + TPB - 1) / TPB;

    const long long out_elems = (long long)tokens * DFULL;
    int write_code = (out_size >= out_elems + tokens) ? 1 : 0;
    float* code_out = out + out_elems;

    int grid = ntiles < 888 ? ntiles : 888;   // 6 resident blocks/SM * 148
    rvq_kernel<<<grid, 128>>>(x, kernel, alpha, out, code_out,
                              tokens, write_code, ntiles);
}

// round 9
// speedup vs baseline: 2.1355x; 2.1355x over previous
#include <cuda_runtime.h>
#include <cstdint>

// RVQ: x[B,S,768] f32, codebook[3,16,256] f32, alpha scalar.
// Per token, per head: argmax_c (x·k_c - 0.5||k_c||^2)  (== argmin sq-dist)
// out = alpha*x + (1-alpha)*k[best]; code = b0 + 16*b1 + 256*b2 (as f32).
//
// Scheme A skeleton: TPW=4, 16-code accumulators, 16-shfl split-exchange +
// REDUX argmax. launch_bounds(128,4) caps regs at 128 -> 4 blocks/SM
// (16 warps; smem 48KB/block limits residency to 4 blocks regardless).

#define NH   3
#define NC   16
#define DHD  256
#define DFULL 768
#define NF4  64             // float4 per code row
#define TPW  4              // tokens per warp
#define NWARPS 4
#define TPB  (TPW * NWARPS) // 16 tokens per block tile
#define FULLMASK 0xffffffffu

__device__ __forceinline__ int swz(int j) { return j ^ (j >> 3); }

__device__ __forceinline__ unsigned fmono(float f) {
    int b = __float_as_int(f);
    return (unsigned)(b ^ ((b >> 31) | 0x80000000));
}

__global__ void __launch_bounds__(128, 4) rvq_kernel(
    const float* __restrict__ x,
    const float* __restrict__ cb,
    const float* __restrict__ alphap,
    float* __restrict__ out,
    float* __restrict__ code_out,
    int tokens, int write_code, int ntiles)
{
    // XOR-swizzled codebook: lane L reads swz(2L), swz(2L+1) conflict-free.
    __shared__ float4 scb[NH * NC * NF4];   // 48 KB

    const int tid = threadIdx.x;
    {
        const float4* cbg = (const float4*)cb;
        #pragma unroll
        for (int g = tid; g < NH * NC * NF4; g += 128) {
            int r = g >> 6, j = g & 63;
            scb[(r << 6) + swz(j)] = cbg[g];
        }
    }
    __syncthreads();

    const int lane = tid & 31;
    const int warp = tid >> 5;
    const int cm   = (lane >> 1) & 15;     // code this lane owns after reduce
    const int sA   = swz(2 * lane);        // lane-constant swizzled offsets
    const int sB   = swz(2 * lane + 1);

    // Half squared norm of code cm, per head (one-time).
    float hn[NH];
    #pragma unroll
    for (int h = 0; h < NH; h++) {
        const float4* row = &scb[(h * NC + cm) << 6];
        float s = 0.f;
        #pragma unroll
        for (int j = 0; j < NF4; j++) {
            float4 k = row[swz((j + 4 * cm) & 63)];
            s = fmaf(k.x, k.x, s); s = fmaf(k.y, k.y, s);
            s = fmaf(k.z, k.z, s); s = fmaf(k.w, k.w, s);
        }
        hn[h] = 0.5f * s;
    }

    const float alpha = *alphap;
    const float beta  = 1.0f - alpha;

    for (int tile = blockIdx.x; tile < ntiles; tile += gridDim.x) {
        int t0 = tile * TPB + warp * TPW;
        if (t0 > tokens - TPW) t0 = tokens - TPW;   // overlap tail: same values
        if (t0 < 0) t0 = 0;

        int pack[TPW];
        #pragma unroll
        for (int t = 0; t < TPW; t++) pack[t] = 0;

        #pragma unroll
        for (int h = 0; h < NH; h++) {
            // Front-batched x: lane holds 8 contiguous dims of head h.
            float4 xa[TPW], xb[TPW];
            const float4* xp0 = (const float4*)(x + t0 * DFULL + h * DHD)
                                + (lane << 1);
            #pragma unroll
            for (int t = 0; t < TPW; t++) {
                xa[t] = xp0[t * 192];
                xb[t] = xp0[t * 192 + 1];
            }

            float acc[TPW][NC];
            #pragma unroll
            for (int t = 0; t < TPW; t++)
                #pragma unroll
                for (int c = 0; c < NC; c++) acc[t][c] = 0.f;

            const float4* hbase = &scb[(h * NC) << 6];
            #pragma unroll
            for (int c = 0; c < NC; c++) {
                float4 ka = hbase[(c << 6) + sA];
                float4 kb = hbase[(c << 6) + sB];
                #pragma unroll
                for (int t = 0; t < TPW; t++) {
                    float a = acc[t][c];
                    a = fmaf(xa[t].x, ka.x, a);
                    a = fmaf(xa[t].y, ka.y, a);
                    a = fmaf(xa[t].z, ka.z, a);
                    a = fmaf(xa[t].w, ka.w, a);
                    a = fmaf(xb[t].x, kb.x, a);
                    a = fmaf(xb[t].y, kb.y, a);
                    a = fmaf(xb[t].z, kb.z, a);
                    a = fmaf(xb[t].w, kb.w, a);
                    acc[t][c] = a;
                }
            }

            // Per token: 16-value split-exchange (16 shfl) + REDUX argmax.
            #pragma unroll
            for (int t = 0; t < TPW; t++) {
                float w8[8];
                {
                    const bool up = (lane & 16) != 0;
                    #pragma unroll
                    for (int j = 0; j < 8; j++) {
                        float snd = up ? acc[t][j]     : acc[t][j + 8];
                        float kp  = up ? acc[t][j + 8] : acc[t][j];
                        w8[j] = kp + __shfl_xor_sync(FULLMASK, snd, 16);
                    }
                }
                float w4[4];
                {
                    const bool up = (lane & 8) != 0;
                    #pragma unroll
                    for (int j = 0; j < 4; j++) {
                        float snd = up ? w8[j]     : w8[j + 4];
                        float kp  = up ? w8[j + 4] : w8[j];
                        w4[j] = kp + __shfl_xor_sync(FULLMASK, snd, 8);
                    }
                }
                float w2[2];
                {
                    const bool up = (lane & 4) != 0;
                    #pragma unroll
                    for (int j = 0; j < 2; j++) {
                        float snd = up ? w4[j]     : w4[j + 2];
                        float kp  = up ? w4[j + 2] : w4[j];
                        w2[j] = kp + __shfl_xor_sync(FULLMASK, snd, 4);
                    }
                }
                float w1;
                {
                    const bool up = (lane & 2) != 0;
                    float snd = up ? w2[0] : w2[1];
                    float kp  = up ? w2[1] : w2[0];
                    w1 = kp + __shfl_xor_sync(FULLMASK, snd, 2);
                }
                w1 += __shfl_xor_sync(FULLMASK, w1, 1);

                float sc = w1 - hn[h];   // lane holds score of code cm
                unsigned u = fmono(sc);
                unsigned umax = __reduce_max_sync(FULLMASK, u);
                unsigned cand = (u == umax) ? (unsigned)cm : 64u;
                int bi = (int)__reduce_min_sync(FULLMASK, cand);
                pack[t] += bi << (4 * h);

                const float4* row = hbase + (bi << 6);
                float4 ka = row[sA];
                float4 kb = row[sB];
                float4 oa, ob;
                oa.x = fmaf(alpha, xa[t].x, beta * ka.x);
                oa.y = fmaf(alpha, xa[t].y, beta * ka.y);
                oa.z = fmaf(alpha, xa[t].z, beta * ka.z);
                oa.w = fmaf(alpha, xa[t].w, beta * ka.w);
                ob.x = fmaf(alpha, xb[t].x, beta * kb.x);
                ob.y = fmaf(alpha, xb[t].y, beta * kb.y);
                ob.z = fmaf(alpha, xb[t].z, beta * kb.z);
                ob.w = fmaf(alpha, xb[t].w, beta * kb.w);
                float4* op = (float4*)(out + (t0 + t) * DFULL + h * DHD)
                             + (lane << 1);
                op[0] = oa;
                op[1] = ob;
            }
        }

        if (write_code && lane == 0) {
            #pragma unroll
            for (int t = 0; t < TPW; t++)
                code_out[t0 + t] = (float)pack[t];
        }
    }
}

extern "C" void kernel_launch(void* const* d_in, const int* in_sizes, int n_in,
                              void* d_out, int out_size)
{
    const float* x      = (const float*)d_in[0];
    const float* kernel = (const float*)d_in[1];
    const float* alpha  = (const float*)d_in[2];
    float* out = (float*)d_out;

    const int tokens = in_sizes[0] / DFULL;        // B*S
    const int ntiles = (tokens + TPB - 1) / TPB;

    const long long out_elems = (long long)tokens * DFULL;
    int write_code = (out_size >= out_elems + tokens) ? 1 : 0;
    float* code_out = out + out_elems;

    int grid = ntiles < 592 ? ntiles : 592;   // 4 resident blocks/SM * 148
    rvq_kernel<<<grid, 128>>>(x, kernel, alpha, out, code_out,
                              tokens, write_code, ntiles);
}

// round 10
// speedup vs baseline: 2.1507x; 1.0071x over previous
#include <cuda_runtime.h>
#include <cstdint>

// RVQ: x[B,S,768] f32, codebook[3,16,256] f32, alpha scalar.
// Per token, per head: argmax_c (x·k_c - 0.5||k_c||^2)  (== argmin sq-dist)
// out = alpha*x + (1-alpha)*k[best]; code = b0 + 16*b1 + 256*b2 (as f32).
//
// Scheme A skeleton: TPW=4, 16-code accumulators, 16-shfl split-exchange +
// REDUX argmax. launch_bounds(128,4) caps regs at 128 -> 4 blocks/SM
// (16 warps; smem 48KB/block limits residency to 4 blocks regardless).

#define NH   3
#define NC   16
#define DHD  256
#define DFULL 768
#define NF4  64             // float4 per code row
#define TPW  4              // tokens per warp
#define NWARPS 4
#define TPB  (TPW * NWARPS) // 16 tokens per block tile
#define FULLMASK 0xffffffffu

__device__ __forceinline__ int swz(int j) { return j ^ (j >> 3); }

__device__ __forceinline__ unsigned fmono(float f) {
    int b = __float_as_int(f);
    return (unsigned)(b ^ ((b >> 31) | 0x80000000));
}

__global__ void __launch_bounds__(128, 4) rvq_kernel(
    const float* __restrict__ x,
    const float* __restrict__ cb,
    const float* __restrict__ alphap,
    float* __restrict__ out,
    float* __restrict__ code_out,
    int tokens, int write_code, int ntiles)
{
    // XOR-swizzled codebook: lane L reads swz(2L), swz(2L+1) conflict-free.
    __shared__ float4 scb[NH * NC * NF4];   // 48 KB

    const int tid = threadIdx.x;
    {
        const float4* cbg = (const float4*)cb;
        #pragma unroll
        for (int g = tid; g < NH * NC * NF4; g += 128) {
            int r = g >> 6, j = g & 63;
            scb[(r << 6) + swz(j)] = cbg[g];
        }
    }
    __syncthreads();

    const int lane = tid & 31;
    const int warp = tid >> 5;
    const int cm   = (lane >> 1) & 15;     // code this lane owns after reduce
    const int sA   = swz(2 * lane);        // lane-constant swizzled offsets
    const int sB   = swz(2 * lane + 1);

    // Half squared norm of code cm, per head (one-time).
    float hn[NH];
    #pragma unroll
    for (int h = 0; h < NH; h++) {
        const float4* row = &scb[(h * NC + cm) << 6];
        float s = 0.f;
        #pragma unroll
        for (int j = 0; j < NF4; j++) {
            float4 k = row[swz((j + 4 * cm) & 63)];
            s = fmaf(k.x, k.x, s); s = fmaf(k.y, k.y, s);
            s = fmaf(k.z, k.z, s); s = fmaf(k.w, k.w, s);
        }
        hn[h] = 0.5f * s;
    }

    const float alpha = *alphap;
    const float beta  = 1.0f - alpha;

    for (int tile = blockIdx.x; tile < ntiles; tile += gridDim.x) {
        int t0 = tile * TPB + warp * TPW;
        if (t0 > tokens - TPW) t0 = tokens - TPW;   // overlap tail: same values
        if (t0 < 0) t0 = 0;

        int pack[TPW];
        #pragma unroll
        for (int t = 0; t < TPW; t++) pack[t] = 0;

        #pragma unroll
        for (int h = 0; h < NH; h++) {
            // Front-batched x: lane holds 8 contiguous dims of head h.
            float4 xa[TPW], xb[TPW];
            const float4* xp0 = (const float4*)(x + t0 * DFULL + h * DHD)
                                + (lane << 1);
            #pragma unroll
            for (int t = 0; t < TPW; t++) {
                xa[t] = xp0[t * 192];
                xb[t] = xp0[t * 192 + 1];
            }

            float acc[TPW][NC];
            #pragma unroll
            for (int t = 0; t < TPW; t++)
                #pragma unroll
                for (int c = 0; c < NC; c++) acc[t][c] = 0.f;

            const float4* hbase = &scb[(h * NC) << 6];
            #pragma unroll
            for (int c = 0; c < NC; c++) {
                float4 ka = hbase[(c << 6) + sA];
                float4 kb = hbase[(c << 6) + sB];
                #pragma unroll
                for (int t = 0; t < TPW; t++) {
                    float a = acc[t][c];
                    a = fmaf(xa[t].x, ka.x, a);
                    a = fmaf(xa[t].y, ka.y, a);
                    a = fmaf(xa[t].z, ka.z, a);
                    a = fmaf(xa[t].w, ka.w, a);
                    a = fmaf(xb[t].x, kb.x, a);
                    a = fmaf(xb[t].y, kb.y, a);
                    a = fmaf(xb[t].z, kb.z, a);
                    a = fmaf(xb[t].w, kb.w, a);
                    acc[t][c] = a;
                }
            }

            // Per token: 16-value split-exchange (16 shfl) + REDUX argmax.
            #pragma unroll
            for (int t = 0; t < TPW; t++) {
                float w8[8];
                {
                    const bool up = (lane & 16) != 0;
                    #pragma unroll
                    for (int j = 0; j < 8; j++) {
                        float snd = up ? acc[t][j]     : acc[t][j + 8];
                        float kp  = up ? acc[t][j + 8] : acc[t][j];
                        w8[j] = kp + __shfl_xor_sync(FULLMASK, snd, 16);
                    }
                }
                float w4[4];
                {
                    const bool up = (lane & 8) != 0;
                    #pragma unroll
                    for (int j = 0; j < 4; j++) {
                        float snd = up ? w8[j]     : w8[j + 4];
                        float kp  = up ? w8[j + 4] : w8[j];
                        w4[j] = kp + __shfl_xor_sync(FULLMASK, snd, 8);
                    }
                }
                float w2[2];
                {
                    const bool up = (lane & 4) != 0;
                    #pragma unroll
                    for (int j = 0; j < 2; j++) {
                        float snd = up ? w4[j]     : w4[j + 2];
                        float kp  = up ? w4[j + 2] : w4[j];
                        w2[j] = kp + __shfl_xor_sync(FULLMASK, snd, 4);
                    }
                }
                float w1;
                {
                    const bool up = (lane & 2) != 0;
                    float snd = up ? w2[0] : w2[1];
                    float kp  = up ? w2[1] : w2[0];
                    w1 = kp + __shfl_xor_sync(FULLMASK, snd, 2);
                }
                w1 += __shfl_xor_sync(FULLMASK, w1, 1);

                float sc = w1 - hn[h];   // lane holds score of code cm
                unsigned u = fmono(sc);
                unsigned umax = __reduce_max_sync(FULLMASK, u);
                unsigned cand = (u == umax) ? (unsigned)cm : 64u;
                int bi = (int)__reduce_min_sync(FULLMASK, cand);
                pack[t] += bi << (4 * h);

                const float4* row = hbase + (bi << 6);
                float4 ka = row[sA];
                float4 kb = row[sB];
                float4 oa, ob;
                oa.x = fmaf(alpha, xa[t].x, beta * ka.x);
                oa.y = fmaf(alpha, xa[t].y, beta * ka.y);
                oa.z = fmaf(alpha, xa[t].z, beta * ka.z);
                oa.w = fmaf(alpha, xa[t].w, beta * ka.w);
                ob.x = fmaf(alpha, xb[t].x, beta * kb.x);
                ob.y = fmaf(alpha, xb[t].y, beta * kb.y);
                ob.z = fmaf(alpha, xb[t].z, beta * kb.z);
                ob.w = fmaf(alpha, xb[t].w, beta * kb.w);
                float4* op = (float4*)(out + (t0 + t) * DFULL + h * DHD)
                             + (lane << 1);
                op[0] = oa;
                op[1] = ob;
            }
        }

        if (write_code && lane == 0) {
            #pragma unroll
            for (int t = 0; t < TPW; t++)
                code_out[t0 + t] = (float)pack[t];
        }
    }
}

extern "C" void kernel_launch(void* const* d_in, const int* in_sizes, int n_in,
                              void* d_out, int out_size)
{
    const float* x      = (const float*)d_in[0];
    const float* kernel = (const float*)d_in[1];
    const float* alpha  = (const float*)d_in[2];
    float* out = (float*)d_out;

    const int tokens = in_sizes[0] / DFULL;        // B*S
    const int ntiles = (tokens + TPB - 1) / TPB;

    const long long out_elems = (long long)tokens * DFULL;
    int write_code = (out_size >= out_elems + tokens) ? 1 : 0;
    float* code_out = out + out_elems;

    int grid = ntiles < 592 ? ntiles : 592;   // 4 resident blocks/SM * 148
    rvq_kernel<<<grid, 128>>>(x, kernel, alpha, out, code_out,
                              tokens, write_code, ntiles);
}